// round 13
// baseline (speedup 1.0000x reference)
#include <cuda_runtime.h>
#include <cuda_fp16.h>
#include <math.h>
#include <stdint.h>

#define NN 2048
#define BB 64
#define DD 64
#define ISZ 130
#define XW (ISZ*BB)          // 8320
#define NDD (NN*DD)          // 131072
#define OUT1 (BB*NDD)        // 8388608
#define HXPART ((size_t)BB*4*NDD)
#define FULL_OUT ((size_t)OUT1 + HXPART)
#define PSZ ((size_t)2048*4096)
#define QSZ ((size_t)4096*NN)
#define KP 144
#define MP ((size_t)NN*64)

// ---------------- scratch ----------------
static __device__ __half g_S1f[(size_t)NN*NN];
static __device__ __half g_S2f[(size_t)NN*NN];
static __device__ __half g_Adf[(size_t)NN*NN];
static __device__ __half g_A2f[(size_t)NN*NN];
static __device__ float g_Ad[(size_t)NN*NN];
static __device__ float g_dinv1[NN];
static __device__ float g_dinv2[NN];
static __device__ float g_cspart[8*NN];
static __device__ float g_X0[(size_t)NN*XW];
static __device__ float g_X1[(size_t)NN*XW];
static __device__ float g_X2[(size_t)NN*XW];
static __device__ __half g_YTh[(size_t)XW*NN];   // YT of x0 / Ad
static __device__ __half g_YTb[(size_t)XW*NN];   // YT of m1 (gemm epilogue)
static __device__ __half g_YTq[4*QSZ];           // YT of the 4 leaf slices (coef folded)
static __device__ __half g_Pq[4*PSZ];            // leaf proj outputs fp16 [n][c]
static __device__ __half g_Xp[MP*KP];
static __device__ __half g_GWT[7*64*KP];
static __device__ float g_gc[(size_t)NN*4096];   // [n][b*64+d]
static __device__ float g_logits[BB*4];
static __device__ float g_wt[BB*4];

__device__ __forceinline__ float* bufAny(int s) {
    if (s == 0) return g_X0;
    if (s == 1) return g_X1;
    if (s == 2) return g_X2;
    return g_Ad;
}

// ---------------- PTX helpers ----------------
__device__ __forceinline__ uint32_t smem_u32(const void* p) {
    uint32_t a;
    asm("{ .reg .u64 t; cvta.to.shared.u64 t, %1; cvt.u32.u64 %0, t; }" : "=r"(a) : "l"(p));
    return a;
}
__device__ __forceinline__ void cp16(uint32_t dst, const void* src) {
    asm volatile("cp.async.cg.shared.global [%0], [%1], 16;" :: "r"(dst), "l"(src) : "memory");
}
__device__ __forceinline__ void cp_commit() { asm volatile("cp.async.commit_group;" ::: "memory"); }
__device__ __forceinline__ void cp_wait2() { asm volatile("cp.async.wait_group 2;" ::: "memory"); }
__device__ __forceinline__ void cp_wait0() { asm volatile("cp.async.wait_group 0;" ::: "memory"); }

__device__ __forceinline__ void ldm_x4(uint32_t* r, uint32_t addr) {
    asm volatile("ldmatrix.sync.aligned.m8n8.x4.shared.b16 {%0,%1,%2,%3}, [%4];"
                 : "=r"(r[0]), "=r"(r[1]), "=r"(r[2]), "=r"(r[3]) : "r"(addr));
}
__device__ __forceinline__ void mma16816h(float* c, const uint32_t* a, uint32_t b0, uint32_t b1) {
    asm volatile(
        "mma.sync.aligned.m16n8k16.row.col.f32.f16.f16.f32 "
        "{%0,%1,%2,%3}, {%4,%5,%6,%7}, {%8,%9}, {%0,%1,%2,%3};"
        : "+f"(c[0]), "+f"(c[1]), "+f"(c[2]), "+f"(c[3])
        : "r"(a[0]), "r"(a[1]), "r"(a[2]), "r"(a[3]), "r"(b0), "r"(b1));
}

// ---------------- support construction ----------------
__global__ void rowsum_dinv_kernel(const float* __restrict__ g) {
    int row = blockIdx.x;
    int tid = threadIdx.x;
    float s = 0.f;
    for (int j = tid; j < NN; j += 256) s += g[(size_t)row*NN + j];
    for (int o = 16; o; o >>= 1) s += __shfl_down_sync(0xffffffffu, s, o);
    __shared__ float red[8];
    if ((tid & 31) == 0) red[tid >> 5] = s;
    __syncthreads();
    if (tid == 0) {
        float t = 0.f;
        #pragma unroll
        for (int w = 0; w < 8; w++) t += red[w];
        g_dinv1[row] = 1.f / (1.f + t);
    }
}

__global__ void colsum_part_kernel(const float* __restrict__ g) {
    int col = blockIdx.x * 256 + threadIdx.x;
    int r0 = blockIdx.y * 256;
    float s = 0.f;
    #pragma unroll 8
    for (int r = 0; r < 256; r++) s += g[(size_t)(r0 + r)*NN + col];
    g_cspart[blockIdx.y*NN + col] = s;
}

__global__ void colsum_fin_kernel() {
    int col = blockIdx.x * 256 + threadIdx.x;
    float s = 0.f;
    #pragma unroll
    for (int y = 0; y < 8; y++) s += g_cspart[y*NN + col];
    g_dinv2[col] = 1.f / (1.f + s);
}

__global__ void build_S1_kernel(const float* __restrict__ g) {
    __shared__ float t[32][33];
    int bi = blockIdx.x * 32;
    int bj = blockIdx.y * 32;
    for (int r = threadIdx.y; r < 32; r += 8)
        t[r][threadIdx.x] = g[(size_t)(bj + r)*NN + bi + threadIdx.x];
    __syncthreads();
    for (int r = threadIdx.y; r < 32; r += 8) {
        int i = bi + r, j = bj + threadIdx.x;
        float dv = g_dinv1[j];
        float v = t[threadIdx.x][r] * dv;
        if (i == j) v += dv;
        g_S1f[(size_t)i*NN + j] = __float2half(v);
    }
}

__global__ void build_S2_kernel(const float* __restrict__ g) {
    int idx = blockIdx.x * 256 + threadIdx.x;
    int i = idx >> 11, j = idx & 2047;
    float v = (g[idx] + (i == j ? 1.f : 0.f)) * g_dinv2[j];
    g_S2f[idx] = __float2half(v);
}

__global__ void adp_kernel(const float* __restrict__ nv1, const float* __restrict__ nv2) {
    int i = blockIdx.x;
    int tid = threadIdx.x;
    __shared__ float v1[10];
    __shared__ float red[40];
    if (tid < 10) v1[tid] = nv1[i*10 + tid];
    __syncthreads();
    float p[8];
    float mx = 0.f;
    #pragma unroll
    for (int c = 0; c < 8; c++) {
        int j = tid + c*256;
        float s = 0.f;
        #pragma unroll
        for (int t = 0; t < 10; t++) s += v1[t] * nv2[t*NN + j];
        s = s > 0.f ? s : 0.f;
        p[c] = s;
        mx = fmaxf(mx, s);
    }
    for (int o = 16; o; o >>= 1) mx = fmaxf(mx, __shfl_xor_sync(0xffffffffu, mx, o));
    if ((tid & 31) == 0) red[tid >> 5] = mx;
    __syncthreads();
    if (tid == 0) {
        float m = red[0];
        #pragma unroll
        for (int w = 1; w < 8; w++) m = fmaxf(m, red[w]);
        red[32] = m;
    }
    __syncthreads();
    mx = red[32];
    float sum = 0.f;
    #pragma unroll
    for (int c = 0; c < 8; c++) { float e = expf(p[c] - mx); p[c] = e; sum += e; }
    for (int o = 16; o; o >>= 1) sum += __shfl_xor_sync(0xffffffffu, sum, o);
    if ((tid & 31) == 0) red[16 + (tid >> 5)] = sum;
    __syncthreads();
    if (tid == 0) {
        float t = 0.f;
        #pragma unroll
        for (int w = 0; w < 8; w++) t += red[16 + w];
        red[33] = 1.f / t;
    }
    __syncthreads();
    float inv = red[33];
    #pragma unroll
    for (int c = 0; c < 8; c++) {
        float v = p[c] * inv;
        size_t idx = (size_t)i*NN + tid + c*256;
        g_Ad[idx] = v;
        g_Adf[idx] = __float2half(v);
    }
}

// transpose fp16: X fp32 [2048 x W] -> g_YTh [W x 2048]
__global__ void xt_f16_kernel(int selX, int W) {
    const float* X = bufAny(selX);
    __shared__ float t[32][33];
    int c0 = blockIdx.x * 32;
    int j0 = blockIdx.y * 32;
    int tx = threadIdx.x;
    for (int r = threadIdx.y; r < 32; r += 8)
        t[r][tx] = X[(size_t)(j0 + r)*W + c0 + tx];
    __syncthreads();
    for (int r = threadIdx.y; r < 32; r += 8)
        g_YTh[(size_t)(c0 + r)*NN + j0 + tx] = __float2half(t[tx][r]);
}

// batched transpose of 4 leaf fp16 slices -> g_YTq (coef folded: slices 0,1 x2)
__global__ void xt_q_kernel() {
    int q = blockIdx.z;
    const __half* X = g_Pq + (size_t)q*PSZ;
    __half* Y = g_YTq + (size_t)q*QSZ;
    __half coef = __float2half(q < 2 ? 2.f : 1.f);
    __shared__ __half t[32][34];
    int c0 = blockIdx.x * 32;
    int j0 = blockIdx.y * 32;
    int tx = threadIdx.x;
    for (int r = threadIdx.y; r < 32; r += 8)
        t[r][tx] = X[(size_t)(j0 + r)*4096 + c0 + tx];
    __syncthreads();
    for (int r = threadIdx.y; r < 32; r += 8)
        Y[(size_t)(c0 + r)*NN + j0 + tx] = __hmul(t[tx][r], coef);
}

// ---------------- x0 build ----------------
__global__ void build_x0_kernel(const float* __restrict__ inputs, const float* __restrict__ hx) {
    size_t total = (size_t)NN * XW;
    for (size_t idx = (size_t)blockIdx.x*256 + threadIdx.x; idx < total; idx += (size_t)gridDim.x*256) {
        int n = (int)(idx / XW);
        int c = (int)(idx - (size_t)n*XW);
        int i = c >> 6, b = c & 63;
        float v;
        if (i < 2) {
            v = inputs[(size_t)b*(NN*2) + n*2 + i];
        } else {
            int q = i - 2;
            int kk = (q < 64) ? 3 : 2;
            int d = q & 63;
            v = hx[(size_t)((b << 2) + kk)*NDD + (size_t)n*64 + d];
        }
        g_X0[idx] = v;
    }
}

// ---------------- gw prep ----------------
// groups: 0:(w0-w2) 1:(w1-w4) 2:(w2) 3:(w3-w6) 4:(w4) 5:(w5) 6:(w6)
__global__ void gw_prep_kernel(const float* __restrict__ gw) {
    int idx = blockIdx.x * 256 + threadIdx.x;
    if (idx >= 7*64*KP) return;
    int i = idx % KP;
    int rd = idx / KP;
    int d = rd & 63;
    int g = rd >> 6;
    const int sA[7] = {0, 1, 2, 3, 4, 5, 6};
    const int sB[7] = {2, 4, -1, 6, -1, -1, -1};
    float v = 0.f;
    if (i < ISZ) {
        v = gw[((size_t)i*7 + sA[g])*64 + d];
        if (sB[g] >= 0) v -= gw[((size_t)i*7 + sB[g])*64 + d];
    }
    g_GWT[idx] = __float2half(v);
}

// ---------------- Xp build ----------------
__global__ void __launch_bounds__(256) xp_kernel(int selX) {
    __shared__ float sx[ISZ*66];
    const float* X = bufAny(selX);
    int n = blockIdx.x;
    int tid = threadIdx.x;
    for (int t = tid; t < XW; t += 256)
        sx[(t >> 6)*66 + (t & 63)] = X[(size_t)n*XW + t];
    __syncthreads();
    for (int t = tid; t < 64*36; t += 256) {
        int b = t / 36, c4 = t % 36;
        int i0 = c4 * 4;
        __half h[4];
        #pragma unroll
        for (int j = 0; j < 4; j++) {
            int i = i0 + j;
            h[j] = (i < ISZ) ? __float2half(sx[i*66 + b]) : __half(__ushort_as_half(0));
        }
        *(uint2*)&g_Xp[(size_t)(n*64 + b)*KP + i0] = *(uint2*)h;
    }
}

// ---------------- tensor-core projection GEMM ----------------
// outSel per group: -2 = gc init (+gb), -1 = gc accumulate, >=10 = fp16 Pq slot (sel-10)
#define TPROW 152
#define TP_A_BYTES (128*TPROW*2)
#define TP_B_BYTES (64*TPROW*2)
#define TPROJ_SMEM (TP_A_BYTES + TP_B_BYTES)

__global__ void __launch_bounds__(256, 2)
tcproj_kernel(int grpBase, int4 outSel, const float* __restrict__ gb) {
    extern __shared__ char smem[];
    uint32_t sb = smem_u32(smem);
    int tid = threadIdx.x;
    int wid = tid >> 5;
    int lane = tid & 31;
    int mb = blockIdx.x;
    int grp = blockIdx.y;
    int sels[4] = {outSel.x, outSel.y, outSel.z, outSel.w};
    int sel = sels[grp];

    {
        const __half* Asrc = g_Xp + (size_t)mb*128*KP;
        for (int t = tid; t < 128*18; t += 256) {
            int r = t / 18, ch = t % 18;
            cp16(sb + (uint32_t)(r*TPROW*2 + ch*16), Asrc + (size_t)r*KP + ch*8);
        }
        const __half* Bsrc = g_GWT + (size_t)(grpBase + grp)*64*KP;
        for (int t = tid; t < 64*18; t += 256) {
            int r = t / 18, ch = t % 18;
            cp16(sb + (uint32_t)(TP_A_BYTES + r*TPROW*2 + ch*16), Bsrc + (size_t)r*KP + ch*8);
        }
    }
    cp_commit();
    cp_wait0();
    __syncthreads();

    int mw = wid & 3;
    int nw = wid >> 2;
    int a_row = lane & 15;
    int a_colb = (lane >> 4) * 16;
    int b_row = ((lane >> 4) & 1) * 8 + (lane & 7);
    int b_colb = ((lane >> 3) & 1) * 16;

    uint32_t aOff = (uint32_t)((mw*32 + a_row) * TPROW * 2) + (uint32_t)a_colb;
    uint32_t bOff = (uint32_t)TP_A_BYTES + (uint32_t)((nw*32 + b_row) * TPROW * 2) + (uint32_t)b_colb;

    float acc[2][4][4];
    #pragma unroll
    for (int mf = 0; mf < 2; mf++)
        #pragma unroll
        for (int nf = 0; nf < 4; nf++)
            #pragma unroll
            for (int e = 0; e < 4; e++) acc[mf][nf][e] = 0.f;

    #pragma unroll
    for (int ks = 0; ks < 9; ks++) {
        uint32_t kb = (uint32_t)(ks*32);
        uint32_t ar[2][4], br[2][4];
        #pragma unroll
        for (int mf = 0; mf < 2; mf++)
            ldm_x4(ar[mf], sb + aOff + (uint32_t)(mf*16*TPROW*2) + kb);
        #pragma unroll
        for (int bg = 0; bg < 2; bg++)
            ldm_x4(br[bg], sb + bOff + (uint32_t)(bg*16*TPROW*2) + kb);
        #pragma unroll
        for (int mf = 0; mf < 2; mf++) {
            #pragma unroll
            for (int bg = 0; bg < 2; bg++) {
                mma16816h(acc[mf][bg*2+0], ar[mf], br[bg][0], br[bg][1]);
                mma16816h(acc[mf][bg*2+1], ar[mf], br[bg][2], br[bg][3]);
            }
        }
    }

    int gid = lane >> 2, tg = lane & 3;
    #pragma unroll
    for (int mf = 0; mf < 2; mf++) {
        int r0g = mb*128 + mw*32 + mf*16 + gid;
        #pragma unroll
        for (int nf = 0; nf < 4; nf++) {
            int col = nw*32 + nf*8 + tg*2;
            size_t i0 = (size_t)r0g*64 + col;
            size_t i1 = i0 + (size_t)8*64;
            float2 v0 = make_float2(acc[mf][nf][0], acc[mf][nf][1]);
            float2 v1 = make_float2(acc[mf][nf][2], acc[mf][nf][3]);
            if (sel >= 10) {
                __half* Pq = g_Pq + (size_t)(sel - 10)*PSZ;
                *(__half2*)&Pq[i0] = __floats2half2_rn(v0.x, v0.y);
                *(__half2*)&Pq[i1] = __floats2half2_rn(v1.x, v1.y);
            } else {
                if (sel == -2) {
                    float2 gbv = *(const float2*)&gb[col];
                    v0.x += gbv.x; v0.y += gbv.y;
                    v1.x += gbv.x; v1.y += gbv.y;
                } else {
                    float2 o0 = *(const float2*)&g_gc[i0];
                    float2 o1 = *(const float2*)&g_gc[i1];
                    v0.x += o0.x; v0.y += o0.y;
                    v1.x += o1.x; v1.y += o1.y;
                }
                *(float2*)&g_gc[i0] = v0;
                *(float2*)&g_gc[i1] = v1;
            }
        }
    }
}

// ---------------- single-product fp16 GEMM ----------------
// mode: 0 = fp32 C; 1 = fp32 C + transposed fp16 -> g_YTb; 2 = fp16 -> g_A2f;
//       3 = Qsum: K=8192 over 4 segments, epilogue g_gc += acc
#define KC 32
#define TROW 80
#define TILEB (128*TROW)
#define STAGEB1 (2*TILEB)
#define GEMM1_SMEM (4*STAGEB1)

__global__ void __launch_bounds__(256, 2)
gemm1_kernel(int selA, int selB, int selC, int W, int mode) {
    extern __shared__ char smem[];
    uint32_t sb = smem_u32(smem);
    int tid = threadIdx.x;
    int wid = tid >> 5;
    int lane = tid & 31;

    const __half* Aseg[4];
    const __half* Bseg[4];
    int nstg;
    if (mode == 3) {
        Aseg[0] = g_S1f; Aseg[1] = g_S2f; Aseg[2] = g_Adf; Aseg[3] = g_A2f;
        Bseg[0] = g_YTq; Bseg[1] = g_YTq + QSZ; Bseg[2] = g_YTq + 2*QSZ; Bseg[3] = g_YTq + 3*QSZ;
        nstg = 256;
    } else {
        const __half* Af = selA == 0 ? g_S1f : (selA == 1 ? g_S2f : (selA == 2 ? g_Adf : g_A2f));
        const __half* Bf = selB == 0 ? g_YTh : g_YTb;
        Aseg[0] = Aseg[1] = Aseg[2] = Aseg[3] = Af;
        Bseg[0] = Bseg[1] = Bseg[2] = Bseg[3] = Bf;
        nstg = 64;
    }
    float* C = bufAny(selC);

    int mBase = blockIdx.x * 128;
    int nBase = blockIdx.y * 128;

    int l_tile[4], l_row[4], l_col[4];
    uint32_t dst[4];
    #pragma unroll
    for (int i = 0; i < 4; i++) {
        int c = tid + i*256;
        int tile = c >> 9;
        int q = c & 511;
        int row = q >> 2, col = q & 3;
        dst[i] = (uint32_t)(tile*TILEB + row*TROW + col*16);
        l_tile[i] = tile;
        l_row[i] = (tile ? nBase : mBase) + row;
        l_col[i] = col*8;
    }

    #pragma unroll
    for (int s = 0; s < 3; s++) {
        uint32_t so = sb + (uint32_t)(s * STAGEB1);
        #pragma unroll
        for (int i = 0; i < 4; i++) {
            const __half* bp = l_tile[i] ? Bseg[0] : Aseg[0];   // stages 0..2 always seg 0
            cp16(so + dst[i], bp + (size_t)l_row[i]*NN + s*KC + l_col[i]);
        }
        cp_commit();
    }

    float acc[4][4][4];
    #pragma unroll
    for (int mf = 0; mf < 4; mf++)
        #pragma unroll
        for (int nf = 0; nf < 4; nf++)
            #pragma unroll
            for (int e = 0; e < 4; e++) acc[mf][nf][e] = 0.f;

    int mw = wid & 1;
    int nw = wid >> 1;
    int a_row = lane & 15;
    int a_colb = (lane >> 4) * 16;
    int b_row = ((lane >> 4) & 1) * 8 + (lane & 7);
    int b_colb = ((lane >> 3) & 1) * 16;

    uint32_t aOff = (uint32_t)((mw*64 + a_row) * TROW) + (uint32_t)a_colb;
    uint32_t bOff = (uint32_t)TILEB + (uint32_t)((nw*32 + b_row) * TROW) + (uint32_t)b_colb;

    for (int s = 0; s < nstg; s++) {
        cp_wait2();
        __syncthreads();
        int sn = s + 3;
        if (sn < nstg) {
            int seg = sn >> 6;
            int ko = (sn & 63) * KC;
            uint32_t so2 = sb + (uint32_t)((sn & 3) * STAGEB1);
            #pragma unroll
            for (int i = 0; i < 4; i++) {
                const __half* bp = l_tile[i] ? Bseg[seg] : Aseg[seg];
                cp16(so2 + dst[i], bp + (size_t)l_row[i]*NN + ko + l_col[i]);
            }
        }
        cp_commit();

        uint32_t so = sb + (uint32_t)((s & 3) * STAGEB1);
        #pragma unroll
        for (int ks = 0; ks < 2; ks++) {
            uint32_t kb = (uint32_t)(ks*32);
            uint32_t ar[4][4], br[2][4];
            #pragma unroll
            for (int mf = 0; mf < 4; mf++)
                ldm_x4(ar[mf], so + aOff + (uint32_t)(mf*16*TROW) + kb);
            #pragma unroll
            for (int bg = 0; bg < 2; bg++)
                ldm_x4(br[bg], so + bOff + (uint32_t)(bg*16*TROW) + kb);
            #pragma unroll
            for (int mf = 0; mf < 4; mf++) {
                #pragma unroll
                for (int bg = 0; bg < 2; bg++) {
                    mma16816h(acc[mf][bg*2+0], ar[mf], br[bg][0], br[bg][1]);
                    mma16816h(acc[mf][bg*2+1], ar[mf], br[bg][2], br[bg][3]);
                }
            }
        }
    }

    int gid = lane >> 2, tg = lane & 3;

    if (mode == 3) {
        #pragma unroll
        for (int mf = 0; mf < 4; mf++) {
            int row0 = mBase + mw*64 + mf*16 + gid;
            #pragma unroll
            for (int nf = 0; nf < 4; nf++) {
                int col = nBase + nw*32 + nf*8 + tg*2;
                size_t i0 = (size_t)row0 * 4096 + col;
                size_t i1 = i0 + (size_t)8 * 4096;
                float2 o0 = *(const float2*)&g_gc[i0];
                float2 o1 = *(const float2*)&g_gc[i1];
                *(float2*)&g_gc[i0] = make_float2(o0.x + acc[mf][nf][0], o0.y + acc[mf][nf][1]);
                *(float2*)&g_gc[i1] = make_float2(o1.x + acc[mf][nf][2], o1.y + acc[mf][nf][3]);
            }
        }
    } else if (mode != 2) {
        #pragma unroll
        for (int mf = 0; mf < 4; mf++) {
            int row0 = mBase + mw*64 + mf*16 + gid;
            #pragma unroll
            for (int nf = 0; nf < 4; nf++) {
                int col = nBase + nw*32 + nf*8 + tg*2;
                size_t i0 = (size_t)row0 * W + col;
                size_t i1 = i0 + (size_t)8 * W;
                *(float2*)&C[i0] = make_float2(acc[mf][nf][0], acc[mf][nf][1]);
                *(float2*)&C[i1] = make_float2(acc[mf][nf][2], acc[mf][nf][3]);
            }
        }
    } else {
        #pragma unroll
        for (int mf = 0; mf < 4; mf++) {
            int row0 = mBase + mw*64 + mf*16 + gid;
            #pragma unroll
            for (int nf = 0; nf < 4; nf++) {
                int col = nBase + nw*32 + nf*8 + tg*2;
                __half2 v0 = __floats2half2_rn(acc[mf][nf][0], acc[mf][nf][1]);
                __half2 v1 = __floats2half2_rn(acc[mf][nf][2], acc[mf][nf][3]);
                *(__half2*)&g_A2f[(size_t)row0 * NN + col] = v0;
                *(__half2*)&g_A2f[(size_t)(row0 + 8) * NN + col] = v1;
            }
        }
    }

    if (mode == 1) {
        cp_wait0();
        __syncthreads();
        __half* st = (__half*)smem;     // pitch 136 halves
        #pragma unroll
        for (int mf = 0; mf < 4; mf++) {
            #pragma unroll
            for (int nf = 0; nf < 4; nf++) {
                int r = mw*64 + mf*16 + gid;
                int c = nw*32 + nf*8 + tg*2;
                st[(c+0)*136 + r]     = __float2half(acc[mf][nf][0]);
                st[(c+1)*136 + r]     = __float2half(acc[mf][nf][1]);
                st[(c+0)*136 + r + 8] = __float2half(acc[mf][nf][2]);
                st[(c+1)*136 + r + 8] = __float2half(acc[mf][nf][3]);
            }
        }
        __syncthreads();
        for (int t = tid; t < 128*16; t += 256) {
            int c = t >> 4, seg = t & 15;
            uint4 v = *(const uint4*)&st[c*136 + seg*8];
            *(uint4*)&g_YTb[(size_t)(nBase + c)*NN + mBase + seg*8] = v;
        }
    }
}

// ---------------- attention ----------------
__global__ void logits_kernel(const float* __restrict__ hx, const float* __restrict__ R,
                              const float* __restrict__ aw, const float* __restrict__ ab) {
    int bk = blockIdx.x;
    int k = bk & 3;
    int tid = threadIdx.x;
    const float* hp = hx + (size_t)bk * NDD;
    const float* rp = R + (size_t)k * NDD;
    float s = 0.f;
    for (int t = tid; t < NDD; t += 256) s += (hp[t] + rp[t]) * aw[t];
    for (int o = 16; o; o >>= 1) s += __shfl_down_sync(0xffffffffu, s, o);
    __shared__ float red[8];
    if ((tid & 31) == 0) red[tid >> 5] = s;
    __syncthreads();
    if (tid == 0) {
        float t = 0.f;
        #pragma unroll
        for (int w = 0; w < 8; w++) t += red[w];
        g_logits[bk] = t + ab[0];
    }
}

__global__ void weight_kernel() {
    int b = threadIdx.x;
    if (b < BB) {
        float l0 = g_logits[b*4+0], l1 = g_logits[b*4+1], l2 = g_logits[b*4+2], l3 = g_logits[b*4+3];
        float m = fmaxf(fmaxf(l0, l1), fmaxf(l2, l3));
        float e0 = expf(l0 - m), e1 = expf(l1 - m), e2 = expf(l2 - m), e3 = expf(l3 - m);
        float inv = 1.f / (e0 + e1 + e2 + e3);
        g_wt[b*4+0] = e0 * inv; g_wt[b*4+1] = e1 * inv;
        g_wt[b*4+2] = e2 * inv; g_wt[b*4+3] = e3 * inv;
    }
}

// ---------------- output ----------------
__global__ void __launch_bounds__(256) final_kernel(const float* __restrict__ W,
                                                    const float* __restrict__ bbias,
                                                    const float* __restrict__ hx,
                                                    const float* __restrict__ R,
                                                    float* __restrict__ out, int write_hx) {
    __shared__ float sW[64*64];
    __shared__ float sg[4*64];
    int tid = threadIdx.x;
    int r0 = blockIdx.x * 4;
    for (int t = tid; t < 4096; t += 256) sW[t] = W[t];
    {
        int row = r0 + (tid >> 6);
        int d = tid & 63;
        int n = row & 2047;
        int b = row >> 11;
        float v = g_gc[(size_t)n*4096 + (size_t)(b*64 + d)];
        sg[tid] = v > 0.f ? v : 0.01f * v;
    }
    __syncthreads();
    int rl = tid >> 6;
    int d = tid & 63;
    int r = r0 + rl;
    int b = r >> 11;
    int n = r & 2047;
    float acc = 0.f;
    #pragma unroll
    for (int e = 0; e < 64; e++) acc += sg[rl*64 + e] * sW[e*64 + d];
    float att = 0.f;
    #pragma unroll
    for (int k = 0; k < 4; k++) {
        float xv = hx[(size_t)((b << 2) + k)*NDD + (size_t)n*64 + d] + R[(size_t)k*NDD + (size_t)n*64 + d];
        att += xv * g_wt[b*4 + k];
    }
    float o = acc + bbias[(size_t)n*64 + d] + att;
    out[(size_t)b*NDD + (size_t)n*64 + d] = o;
    if (write_hx)
        out[(size_t)OUT1 + (size_t)((b << 2) + 3)*NDD + (size_t)n*64 + d] = o;
}

__global__ void hxcopy_kernel(const float* __restrict__ hx, float* __restrict__ out) {
    size_t idx = (size_t)blockIdx.x * 256 + threadIdx.x;
    int b = (int)(idx / (3*(size_t)NDD));
    size_t rem = idx - (size_t)b * (3*(size_t)NDD);
    int kk = (int)(rem / NDD);
    size_t j = rem - (size_t)kk * NDD;
    out[(size_t)OUT1 + (size_t)(b*4 + kk)*NDD + j] = hx[(size_t)(b*4 + kk + 1)*NDD + j];
}

// ---------------- launch ----------------
extern "C" void kernel_launch(void* const* d_in, const int* in_sizes, int n_in,
                              void* d_out, int out_size) {
    const float* inputs = (const float*)d_in[0];
    const float* hx     = (const float*)d_in[1];
    const float* graph  = (const float*)d_in[2];
    const float* nv1    = (const float*)d_in[3];
    const float* nv2    = (const float*)d_in[4];
    const float* W      = (const float*)d_in[5];
    const float* bbias  = (const float*)d_in[6];
    const float* R      = (const float*)d_in[7];
    const float* gw     = (const float*)d_in[8];
    const float* gb     = (const float*)d_in[9];
    const float* aw     = (const float*)d_in[10];
    const float* ab     = (const float*)d_in[11];
    float* out = (float*)d_out;

    int write_hx = ((size_t)out_size >= FULL_OUT) ? 1 : 0;

    cudaFuncSetAttribute(gemm1_kernel, cudaFuncAttributeMaxDynamicSharedMemorySize, GEMM1_SMEM);
    cudaFuncSetAttribute(tcproj_kernel, cudaFuncAttributeMaxDynamicSharedMemorySize, TPROJ_SMEM);

    rowsum_dinv_kernel<<<NN, 256>>>(graph);
    colsum_part_kernel<<<dim3(NN/256, 8), 256>>>(graph);
    colsum_fin_kernel<<<NN/256, 256>>>();
    build_S1_kernel<<<dim3(64, 64), dim3(32, 8)>>>(graph);
    build_S2_kernel<<<(NN*NN)/256, 256>>>(graph);
    adp_kernel<<<NN, 256>>>(nv1, nv2);
    gw_prep_kernel<<<(7*64*KP + 255)/256, 256>>>(gw);

    dim3 gfull(NN/128, XW/128);
    dim3 ga2(NN/128, NN/128);
    dim3 gqsum(NN/128, 4096/128);
    dim3 xfull(XW/32, NN/32);
    dim3 xsq(NN/32, NN/32);
    dim3 xqb(4096/32, NN/32, 4);
    dim3 xblk(32, 8);

    // A2 = A @ A -> g_A2f (fp16 epilogue)
    xt_f16_kernel<<<xsq, xblk>>>(3, NN);
    gemm1_kernel<<<ga2, 256, GEMM1_SMEM>>>(2, 0, 2, NN, 2);

    build_x0_kernel<<<66560, 256>>>(inputs, hx);

    // proj(x0): gc init = gb + proj(x0, w0-w2)
    xp_kernel<<<NN, 256>>>(0);
    tcproj_kernel<<<dim3(1024, 1), 256, TPROJ_SMEM>>>(0, make_int4(-2, 0, 0, 0), gb);

    // m1 = S1 @ x0 -> X1 (+ YTb fp16 transposed epilogue)
    xt_f16_kernel<<<xfull, xblk>>>(0, XW);
    gemm1_kernel<<<gfull, 256, GEMM1_SMEM>>>(0, 0, 1, XW, 1);

    // m3 = S2 @ m1 -> X2 (B = YTb)
    gemm1_kernel<<<gfull, 256, GEMM1_SMEM>>>(1, 1, 2, XW, 0);

    // proj(m1): gc += proj(m1, w1-w4); P2m1 -> Pq0 (sel 10)
    xp_kernel<<<NN, 256>>>(1);
    tcproj_kernel<<<dim3(1024, 2), 256, TPROJ_SMEM>>>(1, make_int4(-1, 10, 0, 0), gb);

    // proj(m3): gc += proj(m3, w3-w6); P4m3->Pq1, P5m3->Pq2, P6m3->Pq3
    xp_kernel<<<NN, 256>>>(2);
    tcproj_kernel<<<dim3(1024, 4), 256, TPROJ_SMEM>>>(3, make_int4(-1, 11, 12, 13), gb);

    // transposes of the 4 leaf slices (coef folded)
    xt_q_kernel<<<xqb, xblk>>>();
    // Qsum: gc += 2*S1@P2 + 2*S2@P4 + Ad@P5 + A2@P6 (concat K=8192)
    gemm1_kernel<<<gqsum, 256, GEMM1_SMEM>>>(0, 0, 0, 4096, 3);

    logits_kernel<<<BB*4, 256>>>(hx, R, aw, ab);
    weight_kernel<<<1, 64>>>();

    final_kernel<<<(BB*NN)/4, 256>>>(W, bbias, hx, R, out, write_hx);
    if (write_hx)
        hxcopy_kernel<<<(unsigned)((size_t)BB*3*NDD/256), 256>>>(hx, out);
}

// round 14
// speedup vs baseline: 1.0632x; 1.0632x over previous
#include <cuda_runtime.h>
#include <cuda_fp16.h>
#include <math.h>
#include <stdint.h>

#define NN 2048
#define BB 64
#define DD 64
#define ISZ 130
#define XW (ISZ*BB)          // 8320
#define NDD (NN*DD)          // 131072
#define OUT1 (BB*NDD)        // 8388608
#define HXPART ((size_t)BB*4*NDD)
#define FULL_OUT ((size_t)OUT1 + HXPART)
#define PSZ ((size_t)2048*4096)
#define QSZ ((size_t)4096*NN)
#define KP 144
#define MP ((size_t)NN*64)

// ---------------- scratch ----------------
static __device__ __half g_S1f[(size_t)NN*NN];
static __device__ __half g_S2f[(size_t)NN*NN];
static __device__ __half g_Adf[(size_t)NN*NN];
static __device__ __half g_A2f[(size_t)NN*NN];
static __device__ float g_dinv1[NN];
static __device__ float g_dinv2[NN];
static __device__ float g_cspart[8*NN];
static __device__ __half g_X0h[(size_t)NN*XW];
static __device__ __half g_X1h[(size_t)NN*XW];
static __device__ __half g_X2h[(size_t)NN*XW];
static __device__ __half g_YTh[(size_t)XW*NN];   // YT of x0 / Ad
static __device__ __half g_YTb[(size_t)XW*NN];   // YT of m1 (gemm epilogue)
static __device__ __half g_YTq[4*QSZ];           // YT of the 4 leaf P slices
static __device__ __half g_Xp[MP*KP];
static __device__ __half g_GWT[7*64*KP];
// P slots 10..23 (13,16,17,18 leaf inputs; 19,20,21,23 Q outputs)
static __device__ float g_P[14*PSZ];
static __device__ float g_gc[(size_t)NN*4096];   // [n][b*64+d]
static __device__ float g_logits[BB*4];
static __device__ float g_wt[BB*4];

__device__ __forceinline__ __half* bufH(int s) {
    if (s == 0) return g_X0h;
    if (s == 1) return g_X1h;
    if (s == 2) return g_X2h;
    return g_Adf;
}

// ---------------- PTX helpers ----------------
__device__ __forceinline__ uint32_t smem_u32(const void* p) {
    uint32_t a;
    asm("{ .reg .u64 t; cvta.to.shared.u64 t, %1; cvt.u32.u64 %0, t; }" : "=r"(a) : "l"(p));
    return a;
}
__device__ __forceinline__ void cp16(uint32_t dst, const void* src) {
    asm volatile("cp.async.cg.shared.global [%0], [%1], 16;" :: "r"(dst), "l"(src) : "memory");
}
__device__ __forceinline__ void cp_commit() { asm volatile("cp.async.commit_group;" ::: "memory"); }
__device__ __forceinline__ void cp_wait2() { asm volatile("cp.async.wait_group 2;" ::: "memory"); }
__device__ __forceinline__ void cp_wait0() { asm volatile("cp.async.wait_group 0;" ::: "memory"); }

__device__ __forceinline__ void ldm_x4(uint32_t* r, uint32_t addr) {
    asm volatile("ldmatrix.sync.aligned.m8n8.x4.shared.b16 {%0,%1,%2,%3}, [%4];"
                 : "=r"(r[0]), "=r"(r[1]), "=r"(r[2]), "=r"(r[3]) : "r"(addr));
}
__device__ __forceinline__ void mma16816h(float* c, const uint32_t* a, uint32_t b0, uint32_t b1) {
    asm volatile(
        "mma.sync.aligned.m16n8k16.row.col.f32.f16.f16.f32 "
        "{%0,%1,%2,%3}, {%4,%5,%6,%7}, {%8,%9}, {%0,%1,%2,%3};"
        : "+f"(c[0]), "+f"(c[1]), "+f"(c[2]), "+f"(c[3])
        : "r"(a[0]), "r"(a[1]), "r"(a[2]), "r"(a[3]), "r"(b0), "r"(b1));
}

// ---------------- support construction ----------------
__global__ void rowsum_dinv_kernel(const float* __restrict__ g) {
    int row = blockIdx.x;
    int tid = threadIdx.x;
    float s = 0.f;
    for (int j = tid; j < NN; j += 256) s += g[(size_t)row*NN + j];
    for (int o = 16; o; o >>= 1) s += __shfl_down_sync(0xffffffffu, s, o);
    __shared__ float red[8];
    if ((tid & 31) == 0) red[tid >> 5] = s;
    __syncthreads();
    if (tid == 0) {
        float t = 0.f;
        #pragma unroll
        for (int w = 0; w < 8; w++) t += red[w];
        g_dinv1[row] = 1.f / (1.f + t);
    }
}

__global__ void colsum_part_kernel(const float* __restrict__ g) {
    int col = blockIdx.x * 256 + threadIdx.x;
    int r0 = blockIdx.y * 256;
    float s = 0.f;
    #pragma unroll 8
    for (int r = 0; r < 256; r++) s += g[(size_t)(r0 + r)*NN + col];
    g_cspart[blockIdx.y*NN + col] = s;
}

__global__ void colsum_fin_kernel() {
    int col = blockIdx.x * 256 + threadIdx.x;
    float s = 0.f;
    #pragma unroll
    for (int y = 0; y < 8; y++) s += g_cspart[y*NN + col];
    g_dinv2[col] = 1.f / (1.f + s);
}

__global__ void build_S1_kernel(const float* __restrict__ g) {
    __shared__ float t[32][33];
    int bi = blockIdx.x * 32;
    int bj = blockIdx.y * 32;
    for (int r = threadIdx.y; r < 32; r += 8)
        t[r][threadIdx.x] = g[(size_t)(bj + r)*NN + bi + threadIdx.x];
    __syncthreads();
    for (int r = threadIdx.y; r < 32; r += 8) {
        int i = bi + r, j = bj + threadIdx.x;
        float dv = g_dinv1[j];
        float v = t[threadIdx.x][r] * dv;
        if (i == j) v += dv;
        g_S1f[(size_t)i*NN + j] = __float2half(v);
    }
}

__global__ void build_S2_kernel(const float* __restrict__ g) {
    int idx = blockIdx.x * 256 + threadIdx.x;
    int i = idx >> 11, j = idx & 2047;
    float v = (g[idx] + (i == j ? 1.f : 0.f)) * g_dinv2[j];
    g_S2f[idx] = __float2half(v);
}

__global__ void adp_kernel(const float* __restrict__ nv1, const float* __restrict__ nv2) {
    int i = blockIdx.x;
    int tid = threadIdx.x;
    __shared__ float v1[10];
    __shared__ float red[40];
    if (tid < 10) v1[tid] = nv1[i*10 + tid];
    __syncthreads();
    float p[8];
    float mx = 0.f;
    #pragma unroll
    for (int c = 0; c < 8; c++) {
        int j = tid + c*256;
        float s = 0.f;
        #pragma unroll
        for (int t = 0; t < 10; t++) s += v1[t] * nv2[t*NN + j];
        s = s > 0.f ? s : 0.f;
        p[c] = s;
        mx = fmaxf(mx, s);
    }
    for (int o = 16; o; o >>= 1) mx = fmaxf(mx, __shfl_xor_sync(0xffffffffu, mx, o));
    if ((tid & 31) == 0) red[tid >> 5] = mx;
    __syncthreads();
    if (tid == 0) {
        float m = red[0];
        #pragma unroll
        for (int w = 1; w < 8; w++) m = fmaxf(m, red[w]);
        red[32] = m;
    }
    __syncthreads();
    mx = red[32];
    float sum = 0.f;
    #pragma unroll
    for (int c = 0; c < 8; c++) { float e = expf(p[c] - mx); p[c] = e; sum += e; }
    for (int o = 16; o; o >>= 1) sum += __shfl_xor_sync(0xffffffffu, sum, o);
    if ((tid & 31) == 0) red[16 + (tid >> 5)] = sum;
    __syncthreads();
    if (tid == 0) {
        float t = 0.f;
        #pragma unroll
        for (int w = 0; w < 8; w++) t += red[16 + w];
        red[33] = 1.f / t;
    }
    __syncthreads();
    float inv = red[33];
    #pragma unroll
    for (int c = 0; c < 8; c++) {
        float v = p[c] * inv;
        g_Adf[(size_t)i*NN + tid + c*256] = __float2half(v);
    }
}

// transpose half->half: X [2048 x W] or [NN x NN] -> g_YTh [W x 2048]
__global__ void xt_f16_kernel(int selX, int W) {
    const __half* X = bufH(selX);
    __shared__ __half t[32][34];
    int c0 = blockIdx.x * 32;
    int j0 = blockIdx.y * 32;
    int tx = threadIdx.x;
    for (int r = threadIdx.y; r < 32; r += 8)
        t[r][tx] = X[(size_t)(j0 + r)*W + c0 + tx];
    __syncthreads();
    for (int r = threadIdx.y; r < 32; r += 8)
        g_YTh[(size_t)(c0 + r)*NN + j0 + tx] = t[tx][r];
}

// batched transpose of 4 leaf P slices (fp32) -> g_YTq quadrants
__global__ void xt_f16_batch_kernel() {
    int q = blockIdx.z;
    int slot = (q == 0) ? 13 : (q == 1) ? 16 : (q == 2) ? 17 : 18;
    const float* X = g_P + (size_t)(slot - 10)*PSZ;
    __half* Y = g_YTq + (size_t)q*QSZ;
    __shared__ float t[32][33];
    int c0 = blockIdx.x * 32;
    int j0 = blockIdx.y * 32;
    int tx = threadIdx.x;
    for (int r = threadIdx.y; r < 32; r += 8)
        t[r][tx] = X[(size_t)(j0 + r)*4096 + c0 + tx];
    __syncthreads();
    for (int r = threadIdx.y; r < 32; r += 8)
        Y[(size_t)(c0 + r)*NN + j0 + tx] = __float2half(t[tx][r]);
}

// ---------------- x0 build (fp16) ----------------
__global__ void build_x0_kernel(const float* __restrict__ inputs, const float* __restrict__ hx) {
    size_t total = (size_t)NN * XW;
    for (size_t idx = (size_t)blockIdx.x*256 + threadIdx.x; idx < total; idx += (size_t)gridDim.x*256) {
        int n = (int)(idx / XW);
        int c = (int)(idx - (size_t)n*XW);
        int i = c >> 6, b = c & 63;
        float v;
        if (i < 2) {
            v = inputs[(size_t)b*(NN*2) + n*2 + i];
        } else {
            int q = i - 2;
            int kk = (q < 64) ? 3 : 2;
            int d = q & 63;
            v = hx[(size_t)((b << 2) + kk)*NDD + (size_t)n*64 + d];
        }
        g_X0h[idx] = __float2half(v);
    }
}

// ---------------- gw prep ----------------
__global__ void gw_prep_kernel(const float* __restrict__ gw) {
    int idx = blockIdx.x * 256 + threadIdx.x;
    if (idx >= 7*64*KP) return;
    int i = idx % KP;
    int rd = idx / KP;
    int d = rd & 63;
    int g = rd >> 6;
    const int sA[7] = {0, 1, 2, 3, 4, 5, 6};
    const int sB[7] = {2, 4, -1, 6, -1, -1, -1};
    float v = 0.f;
    if (i < ISZ) {
        v = gw[((size_t)i*7 + sA[g])*64 + d];
        if (sB[g] >= 0) v -= gw[((size_t)i*7 + sB[g])*64 + d];
    }
    g_GWT[idx] = __float2half(v);
}

// ---------------- Xp build (half in, half out) ----------------
__global__ void __launch_bounds__(256) xp_kernel(int selX) {
    __shared__ __half sx[ISZ*66];
    const __half* X = bufH(selX);
    int n = blockIdx.x;
    int tid = threadIdx.x;
    for (int t = tid; t < XW; t += 256)
        sx[(t >> 6)*66 + (t & 63)] = X[(size_t)n*XW + t];
    __syncthreads();
    for (int t = tid; t < 64*18; t += 256) {
        int b = t / 18, c8 = t % 18;
        int i0 = c8 * 8;
        __half h[8];
        #pragma unroll
        for (int j = 0; j < 8; j++) {
            int i = i0 + j;
            h[j] = (i < ISZ) ? sx[i*66 + b] : __half(__ushort_as_half(0));
        }
        *(uint4*)&g_Xp[(size_t)(n*64 + b)*KP + i0] = *(uint4*)h;
    }
}

// ---------------- tensor-core projection GEMM ----------------
// outSel per group: -2 = gc init (+gb), -1 = gc accumulate, >=10 = P slot (fp32)
#define TPROW 152
#define TP_A_BYTES (128*TPROW*2)
#define TP_B_BYTES (64*TPROW*2)
#define TPROJ_SMEM (TP_A_BYTES + TP_B_BYTES)

__global__ void __launch_bounds__(256, 2)
tcproj_kernel(int grpBase, int4 outSel, const float* __restrict__ gb) {
    extern __shared__ char smem[];
    uint32_t sb = smem_u32(smem);
    int tid = threadIdx.x;
    int wid = tid >> 5;
    int lane = tid & 31;
    int mb = blockIdx.x;
    int grp = blockIdx.y;
    int sels[4] = {outSel.x, outSel.y, outSel.z, outSel.w};
    int sel = sels[grp];

    {
        const __half* Asrc = g_Xp + (size_t)mb*128*KP;
        for (int t = tid; t < 128*18; t += 256) {
            int r = t / 18, ch = t % 18;
            cp16(sb + (uint32_t)(r*TPROW*2 + ch*16), Asrc + (size_t)r*KP + ch*8);
        }
        const __half* Bsrc = g_GWT + (size_t)(grpBase + grp)*64*KP;
        for (int t = tid; t < 64*18; t += 256) {
            int r = t / 18, ch = t % 18;
            cp16(sb + (uint32_t)(TP_A_BYTES + r*TPROW*2 + ch*16), Bsrc + (size_t)r*KP + ch*8);
        }
    }
    cp_commit();
    cp_wait0();
    __syncthreads();

    int mw = wid & 3;
    int nw = wid >> 2;
    int a_row = lane & 15;
    int a_colb = (lane >> 4) * 16;
    int b_row = ((lane >> 4) & 1) * 8 + (lane & 7);
    int b_colb = ((lane >> 3) & 1) * 16;

    uint32_t aOff = (uint32_t)((mw*32 + a_row) * TPROW * 2) + (uint32_t)a_colb;
    uint32_t bOff = (uint32_t)TP_A_BYTES + (uint32_t)((nw*32 + b_row) * TPROW * 2) + (uint32_t)b_colb;

    float acc[2][4][4];
    #pragma unroll
    for (int mf = 0; mf < 2; mf++)
        #pragma unroll
        for (int nf = 0; nf < 4; nf++)
            #pragma unroll
            for (int e = 0; e < 4; e++) acc[mf][nf][e] = 0.f;

    #pragma unroll
    for (int ks = 0; ks < 9; ks++) {
        uint32_t kb = (uint32_t)(ks*32);
        uint32_t ar[2][4], br[2][4];
        #pragma unroll
        for (int mf = 0; mf < 2; mf++)
            ldm_x4(ar[mf], sb + aOff + (uint32_t)(mf*16*TPROW*2) + kb);
        #pragma unroll
        for (int bg = 0; bg < 2; bg++)
            ldm_x4(br[bg], sb + bOff + (uint32_t)(bg*16*TPROW*2) + kb);
        #pragma unroll
        for (int mf = 0; mf < 2; mf++) {
            #pragma unroll
            for (int bg = 0; bg < 2; bg++) {
                mma16816h(acc[mf][bg*2+0], ar[mf], br[bg][0], br[bg][1]);
                mma16816h(acc[mf][bg*2+1], ar[mf], br[bg][2], br[bg][3]);
            }
        }
    }

    int gid = lane >> 2, tg = lane & 3;
    float* Pout = (sel >= 10) ? (g_P + (size_t)(sel - 10)*PSZ) : g_gc;
    #pragma unroll
    for (int mf = 0; mf < 2; mf++) {
        int r0g = mb*128 + mw*32 + mf*16 + gid;
        #pragma unroll
        for (int nf = 0; nf < 4; nf++) {
            int col = nw*32 + nf*8 + tg*2;
            size_t i0 = (size_t)r0g*64 + col;
            size_t i1 = i0 + (size_t)8*64;
            float2 v0 = make_float2(acc[mf][nf][0], acc[mf][nf][1]);
            float2 v1 = make_float2(acc[mf][nf][2], acc[mf][nf][3]);
            if (sel == -2) {
                float2 gbv = *(const float2*)&gb[col];
                v0.x += gbv.x; v0.y += gbv.y;
                v1.x += gbv.x; v1.y += gbv.y;
            } else if (sel == -1) {
                float2 o0 = *(const float2*)&g_gc[i0];
                float2 o1 = *(const float2*)&g_gc[i1];
                v0.x += o0.x; v0.y += o0.y;
                v1.x += o1.x; v1.y += o1.y;
            }
            *(float2*)&Pout[i0] = v0;
            *(float2*)&Pout[i1] = v1;
        }
    }
}

// ---------------- single-product fp16 GEMM ----------------
// mode: 0 = fp32 C (P slot); 1 = fp16 C + transposed fp16 -> g_YTb; 2 = fp16 -> g_A2f; 5 = fp16 C
#define KC 32
#define TROW 80
#define TILEB (128*TROW)
#define STAGEB1 (2*TILEB)
#define GEMM1_SMEM (4*STAGEB1)
#define NSTG 64

__global__ void __launch_bounds__(256, 2)
gemm1_kernel(int selA, int selB, int selC, int W, int mode, int batch) {
    extern __shared__ char smem[];
    uint32_t sb = smem_u32(smem);
    int tid = threadIdx.x;
    int wid = tid >> 5;
    int lane = tid & 31;

    if (batch) {
        int bz = blockIdx.z;
        selA = bz;
        selB = 2 + bz;
        selC = (bz == 0) ? 19 : (bz == 1) ? 20 : (bz == 2) ? 21 : 23;
    }
    const __half* Af = selA == 0 ? g_S1f : (selA == 1 ? g_S2f : (selA == 2 ? g_Adf : g_A2f));
    const __half* Bf = selB == 0 ? g_YTh : (selB == 1 ? g_YTb : g_YTq + (size_t)(selB - 2)*QSZ);

    int mBase = blockIdx.x * 128;
    int nBase = blockIdx.y * 128;

    const __half* src[4];
    uint32_t dst[4];
    #pragma unroll
    for (int i = 0; i < 4; i++) {
        int c = tid + i*256;
        int tile = c >> 9;
        int q = c & 511;
        int row = q >> 2, col = q & 3;
        dst[i] = (uint32_t)(tile*TILEB + row*TROW + col*16);
        const __half* base = (tile == 0) ? Af + (size_t)(mBase + row) * NN
                                         : Bf + (size_t)(nBase + row) * NN;
        src[i] = base + col*8;
    }

    #pragma unroll
    for (int s = 0; s < 3; s++) {
        uint32_t so = sb + (uint32_t)(s * STAGEB1);
        #pragma unroll
        for (int i = 0; i < 4; i++) cp16(so + dst[i], src[i] + s*KC);
        cp_commit();
    }

    float acc[4][4][4];
    #pragma unroll
    for (int mf = 0; mf < 4; mf++)
        #pragma unroll
        for (int nf = 0; nf < 4; nf++)
            #pragma unroll
            for (int e = 0; e < 4; e++) acc[mf][nf][e] = 0.f;

    int mw = wid & 1;
    int nw = wid >> 1;
    int a_row = lane & 15;
    int a_colb = (lane >> 4) * 16;
    int b_row = ((lane >> 4) & 1) * 8 + (lane & 7);
    int b_colb = ((lane >> 3) & 1) * 16;

    uint32_t aOff = (uint32_t)((mw*64 + a_row) * TROW) + (uint32_t)a_colb;
    uint32_t bOff = (uint32_t)TILEB + (uint32_t)((nw*32 + b_row) * TROW) + (uint32_t)b_colb;

    for (int s = 0; s < NSTG; s++) {
        cp_wait2();
        __syncthreads();
        int sn = s + 3;
        if (sn < NSTG) {
            uint32_t so2 = sb + (uint32_t)((sn & 3) * STAGEB1);
            #pragma unroll
            for (int i = 0; i < 4; i++) cp16(so2 + dst[i], src[i] + sn*KC);
        }
        cp_commit();

        uint32_t so = sb + (uint32_t)((s & 3) * STAGEB1);
        #pragma unroll
        for (int ks = 0; ks < 2; ks++) {
            uint32_t kb = (uint32_t)(ks*32);
            uint32_t ar[4][4], br[2][4];
            #pragma unroll
            for (int mf = 0; mf < 4; mf++)
                ldm_x4(ar[mf], so + aOff + (uint32_t)(mf*16*TROW) + kb);
            #pragma unroll
            for (int bg = 0; bg < 2; bg++)
                ldm_x4(br[bg], so + bOff + (uint32_t)(bg*16*TROW) + kb);
            #pragma unroll
            for (int mf = 0; mf < 4; mf++) {
                #pragma unroll
                for (int bg = 0; bg < 2; bg++) {
                    mma16816h(acc[mf][bg*2+0], ar[mf], br[bg][0], br[bg][1]);
                    mma16816h(acc[mf][bg*2+1], ar[mf], br[bg][2], br[bg][3]);
                }
            }
        }
    }

    int gid = lane >> 2, tg = lane & 3;

    if (mode == 0) {
        float* C = g_P + (size_t)(selC - 10)*PSZ;
        #pragma unroll
        for (int mf = 0; mf < 4; mf++) {
            int row0 = mBase + mw*64 + mf*16 + gid;
            #pragma unroll
            for (int nf = 0; nf < 4; nf++) {
                int col = nBase + nw*32 + nf*8 + tg*2;
                size_t i0 = (size_t)row0 * W + col;
                size_t i1 = i0 + (size_t)8 * W;
                *(float2*)&C[i0] = make_float2(acc[mf][nf][0], acc[mf][nf][1]);
                *(float2*)&C[i1] = make_float2(acc[mf][nf][2], acc[mf][nf][3]);
            }
        }
    } else if (mode == 2) {
        #pragma unroll
        for (int mf = 0; mf < 4; mf++) {
            int row0 = mBase + mw*64 + mf*16 + gid;
            #pragma unroll
            for (int nf = 0; nf < 4; nf++) {
                int col = nBase + nw*32 + nf*8 + tg*2;
                __half2 v0 = __floats2half2_rn(acc[mf][nf][0], acc[mf][nf][1]);
                __half2 v1 = __floats2half2_rn(acc[mf][nf][2], acc[mf][nf][3]);
                *(__half2*)&g_A2f[(size_t)row0 * NN + col] = v0;
                *(__half2*)&g_A2f[(size_t)(row0 + 8) * NN + col] = v1;
            }
        }
    } else {
        // mode 1 / 5: fp16 C into X buffer
        __half* Ch = bufH(selC);
        #pragma unroll
        for (int mf = 0; mf < 4; mf++) {
            int row0 = mBase + mw*64 + mf*16 + gid;
            #pragma unroll
            for (int nf = 0; nf < 4; nf++) {
                int col = nBase + nw*32 + nf*8 + tg*2;
                size_t i0 = (size_t)row0 * W + col;
                size_t i1 = i0 + (size_t)8 * W;
                *(__half2*)&Ch[i0] = __floats2half2_rn(acc[mf][nf][0], acc[mf][nf][1]);
                *(__half2*)&Ch[i1] = __floats2half2_rn(acc[mf][nf][2], acc[mf][nf][3]);
            }
        }
    }

    if (mode == 1) {
        cp_wait0();
        __syncthreads();
        __half* st = (__half*)smem;     // pitch 136 halves
        #pragma unroll
        for (int mf = 0; mf < 4; mf++) {
            #pragma unroll
            for (int nf = 0; nf < 4; nf++) {
                int r = mw*64 + mf*16 + gid;
                int c = nw*32 + nf*8 + tg*2;
                st[(c+0)*136 + r]     = __float2half(acc[mf][nf][0]);
                st[(c+1)*136 + r]     = __float2half(acc[mf][nf][1]);
                st[(c+0)*136 + r + 8] = __float2half(acc[mf][nf][2]);
                st[(c+1)*136 + r + 8] = __float2half(acc[mf][nf][3]);
            }
        }
        __syncthreads();
        for (int t = tid; t < 128*16; t += 256) {
            int c = t >> 4, seg = t & 15;
            uint4 v = *(const uint4*)&st[c*136 + seg*8];
            *(uint4*)&g_YTb[(size_t)(nBase + c)*NN + mBase + seg*8] = v;
        }
    }
}

// ---------------- attention ----------------
__global__ void logits_kernel(const float* __restrict__ hx, const float* __restrict__ R,
                              const float* __restrict__ aw, const float* __restrict__ ab) {
    int bk = blockIdx.x;
    int k = bk & 3;
    int tid = threadIdx.x;
    const float* hp = hx + (size_t)bk * NDD;
    const float* rp = R + (size_t)k * NDD;
    float s = 0.f;
    for (int t = tid; t < NDD; t += 256) s += (hp[t] + rp[t]) * aw[t];
    for (int o = 16; o; o >>= 1) s += __shfl_down_sync(0xffffffffu, s, o);
    __shared__ float red[8];
    if ((tid & 31) == 0) red[tid >> 5] = s;
    __syncthreads();
    if (tid == 0) {
        float t = 0.f;
        #pragma unroll
        for (int w = 0; w < 8; w++) t += red[w];
        g_logits[bk] = t + ab[0];
    }
}

__global__ void weight_kernel() {
    int b = threadIdx.x;
    if (b < BB) {
        float l0 = g_logits[b*4+0], l1 = g_logits[b*4+1], l2 = g_logits[b*4+2], l3 = g_logits[b*4+3];
        float m = fmaxf(fmaxf(l0, l1), fmaxf(l2, l3));
        float e0 = expf(l0 - m), e1 = expf(l1 - m), e2 = expf(l2 - m), e3 = expf(l3 - m);
        float inv = 1.f / (e0 + e1 + e2 + e3);
        g_wt[b*4+0] = e0 * inv; g_wt[b*4+1] = e1 * inv;
        g_wt[b*4+2] = e2 * inv; g_wt[b*4+3] = e3 * inv;
    }
}

// ---------------- output (fused combine) ----------------
__global__ void __launch_bounds__(256) final_kernel(const float* __restrict__ W,
                                                    const float* __restrict__ bbias,
                                                    const float* __restrict__ hx,
                                                    const float* __restrict__ R,
                                                    float* __restrict__ out, int write_hx) {
    __shared__ float sW[64*64];
    __shared__ float sg[4*64];
    int tid = threadIdx.x;
    int r0 = blockIdx.x * 4;
    for (int t = tid; t < 4096; t += 256) sW[t] = W[t];
    {
        int row = r0 + (tid >> 6);
        int d = tid & 63;
        int n = row & 2047;
        int b = row >> 11;
        size_t p = (size_t)n*4096 + (size_t)(b*64 + d);
        float v = g_gc[p]
                + 2.f*g_P[9*PSZ + p]      // Q2
                + 2.f*g_P[10*PSZ + p]     // Q4
                + g_P[11*PSZ + p]         // Q5
                + g_P[13*PSZ + p];        // Q6
        sg[tid] = v > 0.f ? v : 0.01f * v;
    }
    __syncthreads();
    int rl = tid >> 6;
    int d = tid & 63;
    int r = r0 + rl;
    int b = r >> 11;
    int n = r & 2047;
    float acc = 0.f;
    #pragma unroll
    for (int e = 0; e < 64; e++) acc += sg[rl*64 + e] * sW[e*64 + d];
    float att = 0.f;
    #pragma unroll
    for (int k = 0; k < 4; k++) {
        float xv = hx[(size_t)((b << 2) + k)*NDD + (size_t)n*64 + d] + R[(size_t)k*NDD + (size_t)n*64 + d];
        att += xv * g_wt[b*4 + k];
    }
    float o = acc + bbias[(size_t)n*64 + d] + att;
    out[(size_t)b*NDD + (size_t)n*64 + d] = o;
    if (write_hx)
        out[(size_t)OUT1 + (size_t)((b << 2) + 3)*NDD + (size_t)n*64 + d] = o;
}

__global__ void hxcopy_kernel(const float* __restrict__ hx, float* __restrict__ out) {
    size_t idx = (size_t)blockIdx.x * 256 + threadIdx.x;
    int b = (int)(idx / (3*(size_t)NDD));
    size_t rem = idx - (size_t)b * (3*(size_t)NDD);
    int kk = (int)(rem / NDD);
    size_t j = rem - (size_t)kk * NDD;
    out[(size_t)OUT1 + (size_t)(b*4 + kk)*NDD + j] = hx[(size_t)(b*4 + kk + 1)*NDD + j];
}

// ---------------- launch ----------------
extern "C" void kernel_launch(void* const* d_in, const int* in_sizes, int n_in,
                              void* d_out, int out_size) {
    const float* inputs = (const float*)d_in[0];
    const float* hx     = (const float*)d_in[1];
    const float* graph  = (const float*)d_in[2];
    const float* nv1    = (const float*)d_in[3];
    const float* nv2    = (const float*)d_in[4];
    const float* W      = (const float*)d_in[5];
    const float* bbias  = (const float*)d_in[6];
    const float* R      = (const float*)d_in[7];
    const float* gw     = (const float*)d_in[8];
    const float* gb     = (const float*)d_in[9];
    const float* aw     = (const float*)d_in[10];
    const float* ab     = (const float*)d_in[11];
    float* out = (float*)d_out;

    int write_hx = ((size_t)out_size >= FULL_OUT) ? 1 : 0;

    cudaFuncSetAttribute(gemm1_kernel, cudaFuncAttributeMaxDynamicSharedMemorySize, GEMM1_SMEM);
    cudaFuncSetAttribute(tcproj_kernel, cudaFuncAttributeMaxDynamicSharedMemorySize, TPROJ_SMEM);

    rowsum_dinv_kernel<<<NN, 256>>>(graph);
    colsum_part_kernel<<<dim3(NN/256, 8), 256>>>(graph);
    colsum_fin_kernel<<<NN/256, 256>>>();
    build_S1_kernel<<<dim3(64, 64), dim3(32, 8)>>>(graph);
    build_S2_kernel<<<(NN*NN)/256, 256>>>(graph);
    adp_kernel<<<NN, 256>>>(nv1, nv2);
    gw_prep_kernel<<<(7*64*KP + 255)/256, 256>>>(gw);

    dim3 gfull(NN/128, XW/128);
    dim3 ga2(NN/128, NN/128);
    dim3 gleaf(NN/128, 4096/128, 4);
    dim3 xfull(XW/32, NN/32);
    dim3 xsq(NN/32, NN/32);
    dim3 xqb(4096/32, NN/32, 4);
    dim3 xblk(32, 8);

    // A2 = A @ A -> g_A2f (B operand = transpose of Adf)
    xt_f16_kernel<<<xsq, xblk>>>(3, NN);
    gemm1_kernel<<<ga2, 256, GEMM1_SMEM>>>(2, 0, 2, NN, 2, 0);

    build_x0_kernel<<<66560, 256>>>(inputs, hx);

    // proj(x0): gc init = gb + proj(x0, w0-w2)
    xp_kernel<<<NN, 256>>>(0);
    tcproj_kernel<<<dim3(1024, 1), 256, TPROJ_SMEM>>>(0, make_int4(-2, 0, 0, 0), gb);

    // m1 = S1 @ x0 -> X1h (+ YTb fp16 transposed epilogue)
    xt_f16_kernel<<<xfull, xblk>>>(0, XW);
    gemm1_kernel<<<gfull, 256, GEMM1_SMEM>>>(0, 0, 1, XW, 1, 0);

    // m3 = S2 @ m1 -> X2h (B = YTb)
    gemm1_kernel<<<gfull, 256, GEMM1_SMEM>>>(1, 1, 2, XW, 5, 0);

    // proj(m1): gc += proj(m1, w1-w4); P2m1 -> slot 13
    xp_kernel<<<NN, 256>>>(1);
    tcproj_kernel<<<dim3(1024, 2), 256, TPROJ_SMEM>>>(1, make_int4(-1, 13, 0, 0), gb);

    // proj(m3): gc += proj(m3, w3-w6); P4m3->16, P5m3->17, P6m3->18
    xp_kernel<<<NN, 256>>>(2);
    tcproj_kernel<<<dim3(1024, 4), 256, TPROJ_SMEM>>>(3, make_int4(-1, 16, 17, 18), gb);

    // batched transposes of the 4 leaf slices
    xt_f16_batch_kernel<<<xqb, xblk>>>();
    // batched leaf GEMMs: Q2, Q4, Q5, Q6 (fp32 -> P slots 19,20,21,23)
    gemm1_kernel<<<gleaf, 256, GEMM1_SMEM>>>(0, 0, 0, 4096, 0, 1);

    logits_kernel<<<BB*4, 256>>>(hx, R, aw, ab);
    weight_kernel<<<1, 64>>>();

    final_kernel<<<(BB*NN)/4, 256>>>(W, bbias, hx, R, out, write_hx);
    if (write_hx)
        hxcopy_kernel<<<(unsigned)((size_t)BB*3*NDD/256), 256>>>(hx, out);
}

// round 17
// speedup vs baseline: 1.1501x; 1.0817x over previous
#include <cuda_runtime.h>
#include <cuda_fp16.h>
#include <math.h>
#include <stdint.h>

#define NN 2048
#define BB 64
#define DD 64
#define ISZ 130
#define XW (ISZ*BB)          // 8320
#define NDD (NN*DD)          // 131072
#define OUT1 (BB*NDD)        // 8388608
#define HXPART ((size_t)BB*4*NDD)
#define FULL_OUT ((size_t)OUT1 + HXPART)
#define PSZ ((size_t)2048*4096)
#define QSZ ((size_t)4096*NN)
#define KP 144
#define MP ((size_t)NN*64)
#define X0BLKS 66560

// ---------------- scratch ----------------
static __device__ __half g_S1f[(size_t)NN*NN];
static __device__ __half g_S2f[(size_t)NN*NN];
static __device__ __half g_Adf[(size_t)NN*NN];
static __device__ __half g_A2f[(size_t)NN*NN];
static __device__ float g_dinv1[NN];
static __device__ float g_dinv2[NN];
static __device__ float g_cspart[8*NN];
static __device__ __half g_X0h[(size_t)NN*XW];
static __device__ __half g_X1h[(size_t)NN*XW];
static __device__ __half g_X2h[(size_t)NN*XW];
static __device__ __half g_YTh[(size_t)XW*NN];
static __device__ __half g_YTa[(size_t)NN*NN];
static __device__ __half g_YTb[(size_t)XW*NN];
static __device__ __half g_YTq[4*QSZ];
static __device__ __half g_Xp[MP*KP];
static __device__ __half g_Xp2[MP*KP];
static __device__ __half g_GWT[7*64*KP];
static __device__ float g_P[14*PSZ];
static __device__ float g_gc[(size_t)NN*4096];
static __device__ float g_logits[BB*4];

__device__ __forceinline__ __half* bufH(int s) {
    if (s == 0) return g_X0h;
    if (s == 1) return g_X1h;
    if (s == 2) return g_X2h;
    return g_Adf;
}

// ---------------- PTX helpers ----------------
__device__ __forceinline__ uint32_t smem_u32(const void* p) {
    uint32_t a;
    asm("{ .reg .u64 t; cvta.to.shared.u64 t, %1; cvt.u32.u64 %0, t; }" : "=r"(a) : "l"(p));
    return a;
}
__device__ __forceinline__ void cp16(uint32_t dst, const void* src) {
    asm volatile("cp.async.cg.shared.global [%0], [%1], 16;" :: "r"(dst), "l"(src) : "memory");
}
__device__ __forceinline__ void cp_commit() { asm volatile("cp.async.commit_group;" ::: "memory"); }
__device__ __forceinline__ void cp_wait2() { asm volatile("cp.async.wait_group 2;" ::: "memory"); }
__device__ __forceinline__ void cp_wait0() { asm volatile("cp.async.wait_group 0;" ::: "memory"); }

__device__ __forceinline__ void ldm_x4(uint32_t* r, uint32_t addr) {
    asm volatile("ldmatrix.sync.aligned.m8n8.x4.shared.b16 {%0,%1,%2,%3}, [%4];"
                 : "=r"(r[0]), "=r"(r[1]), "=r"(r[2]), "=r"(r[3]) : "r"(addr));
}
__device__ __forceinline__ void mma16816h(float* c, const uint32_t* a, uint32_t b0, uint32_t b1) {
    asm volatile(
        "mma.sync.aligned.m16n8k16.row.col.f32.f16.f16.f32 "
        "{%0,%1,%2,%3}, {%4,%5,%6,%7}, {%8,%9}, {%0,%1,%2,%3};"
        : "+f"(c[0]), "+f"(c[1]), "+f"(c[2]), "+f"(c[3])
        : "r"(a[0]), "r"(a[1]), "r"(a[2]), "r"(a[3]), "r"(b0), "r"(b1));
}

// ---------------- support construction ----------------
__global__ void rowsum_dinv_kernel(const float* __restrict__ g) {
    int row = blockIdx.x;
    int tid = threadIdx.x;
    float s = 0.f;
    for (int j = tid; j < NN; j += 256) s += g[(size_t)row*NN + j];
    for (int o = 16; o; o >>= 1) s += __shfl_down_sync(0xffffffffu, s, o);
    __shared__ float red[8];
    if ((tid & 31) == 0) red[tid >> 5] = s;
    __syncthreads();
    if (tid == 0) {
        float t = 0.f;
        #pragma unroll
        for (int w = 0; w < 8; w++) t += red[w];
        g_dinv1[row] = 1.f / (1.f + t);
    }
}

__global__ void colsum_part_kernel(const float* __restrict__ g) {
    int col = blockIdx.x * 256 + threadIdx.x;
    int r0 = blockIdx.y * 256;
    float s = 0.f;
    #pragma unroll 8
    for (int r = 0; r < 256; r++) s += g[(size_t)(r0 + r)*NN + col];
    g_cspart[blockIdx.y*NN + col] = s;
}

__global__ void colsum_fin_kernel() {
    int col = blockIdx.x * 256 + threadIdx.x;
    float s = 0.f;
    #pragma unroll
    for (int y = 0; y < 8; y++) s += g_cspart[y*NN + col];
    g_dinv2[col] = 1.f / (1.f + s);
}

__global__ void build_S1_kernel(const float* __restrict__ g) {
    __shared__ float t[32][33];
    int bi = blockIdx.x * 32;
    int bj = blockIdx.y * 32;
    for (int r = threadIdx.y; r < 32; r += 8)
        t[r][threadIdx.x] = g[(size_t)(bj + r)*NN + bi + threadIdx.x];
    __syncthreads();
    for (int r = threadIdx.y; r < 32; r += 8) {
        int i = bi + r, j = bj + threadIdx.x;
        float dv = g_dinv1[j];
        float v = t[threadIdx.x][r] * dv;
        if (i == j) v += dv;
        g_S1f[(size_t)i*NN + j] = __float2half(v);
    }
}

__global__ void build_S2_kernel(const float* __restrict__ g) {
    int idx = blockIdx.x * 256 + threadIdx.x;
    int i = idx >> 11, j = idx & 2047;
    float v = (g[idx] + (i == j ? 1.f : 0.f)) * g_dinv2[j];
    g_S2f[idx] = __float2half(v);
}

__global__ void adp_kernel(const float* __restrict__ nv1, const float* __restrict__ nv2) {
    int i = blockIdx.x;
    int tid = threadIdx.x;
    __shared__ float v1[10];
    __shared__ float red[40];
    if (tid < 10) v1[tid] = nv1[i*10 + tid];
    __syncthreads();
    float p[8];
    float mx = 0.f;
    #pragma unroll
    for (int c = 0; c < 8; c++) {
        int j = tid + c*256;
        float s = 0.f;
        #pragma unroll
        for (int t = 0; t < 10; t++) s += v1[t] * nv2[t*NN + j];
        s = s > 0.f ? s : 0.f;
        p[c] = s;
        mx = fmaxf(mx, s);
    }
    for (int o = 16; o; o >>= 1) mx = fmaxf(mx, __shfl_xor_sync(0xffffffffu, mx, o));
    if ((tid & 31) == 0) red[tid >> 5] = mx;
    __syncthreads();
    if (tid == 0) {
        float m = red[0];
        #pragma unroll
        for (int w = 1; w < 8; w++) m = fmaxf(m, red[w]);
        red[32] = m;
    }
    __syncthreads();
    mx = red[32];
    float sum = 0.f;
    #pragma unroll
    for (int c = 0; c < 8; c++) { float e = expf(p[c] - mx); p[c] = e; sum += e; }
    for (int o = 16; o; o >>= 1) sum += __shfl_xor_sync(0xffffffffu, sum, o);
    if ((tid & 31) == 0) red[16 + (tid >> 5)] = sum;
    __syncthreads();
    if (tid == 0) {
        float t = 0.f;
        #pragma unroll
        for (int w = 0; w < 8; w++) t += red[16 + w];
        red[33] = 1.f / t;
    }
    __syncthreads();
    float inv = red[33];
    #pragma unroll
    for (int c = 0; c < 8; c++) {
        float v = p[c] * inv;
        g_Adf[(size_t)i*NN + tid + c*256] = __float2half(v);
    }
}

// combined transpose: x0 -> YTh and Adf -> YTa in one launch
__global__ void xt_comb_kernel() {
    const __half* X;
    __half* Y;
    int W;
    int bx = blockIdx.x;
    if (bx < XW/32) { X = g_X0h; Y = g_YTh; W = XW; }
    else            { X = g_Adf; Y = g_YTa; W = NN; bx -= XW/32; }
    __shared__ __half t[32][34];
    int c0 = bx * 32;
    int j0 = blockIdx.y * 32;
    int tx = threadIdx.x;
    for (int r = threadIdx.y; r < 32; r += 8)
        t[r][tx] = X[(size_t)(j0 + r)*W + c0 + tx];
    __syncthreads();
    for (int r = threadIdx.y; r < 32; r += 8)
        Y[(size_t)(c0 + r)*NN + j0 + tx] = t[tx][r];
}

__global__ void xt_f16_batch_kernel() {
    int q = blockIdx.z;
    int slot = (q == 0) ? 13 : (q == 1) ? 16 : (q == 2) ? 17 : 18;
    const float* X = g_P + (size_t)(slot - 10)*PSZ;
    __half* Y = g_YTq + (size_t)q*QSZ;
    __shared__ float t[32][33];
    int c0 = blockIdx.x * 32;
    int j0 = blockIdx.y * 32;
    int tx = threadIdx.x;
    for (int r = threadIdx.y; r < 32; r += 8)
        t[r][tx] = X[(size_t)(j0 + r)*4096 + c0 + tx];
    __syncthreads();
    for (int r = threadIdx.y; r < 32; r += 8)
        Y[(size_t)(c0 + r)*NN + j0 + tx] = __float2half(t[tx][r]);
}

// ---------------- x0 build (fp16) fused with attention logits ----------------
__global__ void build_x0_logits_kernel(const float* __restrict__ inputs, const float* __restrict__ hx,
                                       const float* __restrict__ R,
                                       const float* __restrict__ aw, const float* __restrict__ ab) {
    int tid = threadIdx.x;
    if (blockIdx.x < X0BLKS) {
        size_t idx = (size_t)blockIdx.x*256 + tid;
        int n = (int)(idx / XW);
        int c = (int)(idx - (size_t)n*XW);
        int i = c >> 6, b = c & 63;
        float v;
        if (i < 2) {
            v = inputs[(size_t)b*(NN*2) + n*2 + i];
        } else {
            int q = i - 2;
            int kk = (q < 64) ? 3 : 2;
            int d = q & 63;
            v = hx[(size_t)((b << 2) + kk)*NDD + (size_t)n*64 + d];
        }
        g_X0h[idx] = __float2half(v);
    } else {
        int bk = blockIdx.x - X0BLKS;      // b*4+k
        int k = bk & 3;
        const float* hp = hx + (size_t)bk * NDD;
        const float* rp = R + (size_t)k * NDD;
        float s = 0.f;
        for (int t = tid; t < NDD; t += 256) s += (hp[t] + rp[t]) * aw[t];
        for (int o = 16; o; o >>= 1) s += __shfl_down_sync(0xffffffffu, s, o);
        __shared__ float red[8];
        if ((tid & 31) == 0) red[tid >> 5] = s;
        __syncthreads();
        if (tid == 0) {
            float t = 0.f;
            #pragma unroll
            for (int w = 0; w < 8; w++) t += red[w];
            g_logits[bk] = t + ab[0];
        }
    }
}

// ---------------- gw prep ----------------
__global__ void gw_prep_kernel(const float* __restrict__ gw) {
    int idx = blockIdx.x * 256 + threadIdx.x;
    if (idx >= 7*64*KP) return;
    int i = idx % KP;
    int rd = idx / KP;
    int d = rd & 63;
    int g = rd >> 6;
    const int sA[7] = {0, 1, 2, 3, 4, 5, 6};
    const int sB[7] = {2, 4, -1, 6, -1, -1, -1};
    float v = 0.f;
    if (i < ISZ) {
        v = gw[((size_t)i*7 + sA[g])*64 + d];
        if (sB[g] >= 0) v -= gw[((size_t)i*7 + sB[g])*64 + d];
    }
    g_GWT[idx] = __float2half(v);
}

// ---------------- Xp build ----------------
__global__ void __launch_bounds__(256) xp_kernel(int selX, int dual) {
    __shared__ __half sx[ISZ*66];
    const __half* X;
    __half* Xp;
    if (dual) {
        X = blockIdx.y == 0 ? g_X1h : g_X2h;
        Xp = blockIdx.y == 0 ? g_Xp : g_Xp2;
    } else {
        X = bufH(selX);
        Xp = g_Xp;
    }
    int n = blockIdx.x;
    int tid = threadIdx.x;
    for (int t = tid; t < XW; t += 256)
        sx[(t >> 6)*66 + (t & 63)] = X[(size_t)n*XW + t];
    __syncthreads();
    for (int t = tid; t < 64*18; t += 256) {
        int b = t / 18, c8 = t % 18;
        int i0 = c8 * 8;
        __half h[8];
        #pragma unroll
        for (int j = 0; j < 8; j++) {
            int i = i0 + j;
            h[j] = (i < ISZ) ? sx[i*66 + b] : __half(__ushort_as_half(0));
        }
        *(uint4*)&Xp[(size_t)(n*64 + b)*KP + i0] = *(uint4*)h;
    }
}

// ---------------- tensor-core projection GEMM ----------------
#define TPROW 152
#define TP_A_BYTES (128*TPROW*2)
#define TP_B_BYTES (64*TPROW*2)
#define TPROJ_SMEM (TP_A_BYTES + TP_B_BYTES)

__global__ void __launch_bounds__(256, 2)
tcproj_kernel(int fused, int grpBase, int4 outSel, const float* __restrict__ gb) {
    extern __shared__ char smem[];
    uint32_t sb = smem_u32(smem);
    int tid = threadIdx.x;
    int wid = tid >> 5;
    int lane = tid & 31;
    int mb = blockIdx.x;
    int grp = blockIdx.y;
    int sel, gwg;
    const __half* XpSrc;
    if (fused) {
        gwg = grp + 1;
        XpSrc = (grp < 2) ? g_Xp : g_Xp2;
        sel = (grp == 0) ? 15 : (grp == 1) ? 13 : (grp == 2) ? -1 : (13 + grp);
    } else {
        gwg = grpBase + grp;
        XpSrc = g_Xp;
        int sels[4] = {outSel.x, outSel.y, outSel.z, outSel.w};
        sel = sels[grp];
    }

    {
        const __half* Asrc = XpSrc + (size_t)mb*128*KP;
        for (int t = tid; t < 128*18; t += 256) {
            int r = t / 18, ch = t % 18;
            cp16(sb + (uint32_t)(r*TPROW*2 + ch*16), Asrc + (size_t)r*KP + ch*8);
        }
        const __half* Bsrc = g_GWT + (size_t)gwg*64*KP;
        for (int t = tid; t < 64*18; t += 256) {
            int r = t / 18, ch = t % 18;
            cp16(sb + (uint32_t)(TP_A_BYTES + r*TPROW*2 + ch*16), Bsrc + (size_t)r*KP + ch*8);
        }
    }
    cp_commit();
    cp_wait0();
    __syncthreads();

    int mw = wid & 3;
    int nw = wid >> 2;
    int a_row = lane & 15;
    int a_colb = (lane >> 4) * 16;
    int b_row = ((lane >> 4) & 1) * 8 + (lane & 7);
    int b_colb = ((lane >> 3) & 1) * 16;

    uint32_t aOff = (uint32_t)((mw*32 + a_row) * TPROW * 2) + (uint32_t)a_colb;
    uint32_t bOff = (uint32_t)TP_A_BYTES + (uint32_t)((nw*32 + b_row) * TPROW * 2) + (uint32_t)b_colb;

    float acc[2][4][4];
    #pragma unroll
    for (int mf = 0; mf < 2; mf++)
        #pragma unroll
        for (int nf = 0; nf < 4; nf++)
            #pragma unroll
            for (int e = 0; e < 4; e++) acc[mf][nf][e] = 0.f;

    #pragma unroll
    for (int ks = 0; ks < 9; ks++) {
        uint32_t kb = (uint32_t)(ks*32);
        uint32_t ar[2][4], br[2][4];
        #pragma unroll
        for (int mf = 0; mf < 2; mf++)
            ldm_x4(ar[mf], sb + aOff + (uint32_t)(mf*16*TPROW*2) + kb);
        #pragma unroll
        for (int bg = 0; bg < 2; bg++)
            ldm_x4(br[bg], sb + bOff + (uint32_t)(bg*16*TPROW*2) + kb);
        #pragma unroll
        for (int mf = 0; mf < 2; mf++) {
            #pragma unroll
            for (int bg = 0; bg < 2; bg++) {
                mma16816h(acc[mf][bg*2+0], ar[mf], br[bg][0], br[bg][1]);
                mma16816h(acc[mf][bg*2+1], ar[mf], br[bg][2], br[bg][3]);
            }
        }
    }

    int gid = lane >> 2, tg = lane & 3;
    float* Pout = (sel >= 10) ? (g_P + (size_t)(sel - 10)*PSZ) : g_gc;
    #pragma unroll
    for (int mf = 0; mf < 2; mf++) {
        int r0g = mb*128 + mw*32 + mf*16 + gid;
        #pragma unroll
        for (int nf = 0; nf < 4; nf++) {
            int col = nw*32 + nf*8 + tg*2;
            size_t i0 = (size_t)r0g*64 + col;
            size_t i1 = i0 + (size_t)8*64;
            float2 v0 = make_float2(acc[mf][nf][0], acc[mf][nf][1]);
            float2 v1 = make_float2(acc[mf][nf][2], acc[mf][nf][3]);
            if (sel == -2) {
                float2 gbv = *(const float2*)&gb[col];
                v0.x += gbv.x; v0.y += gbv.y;
                v1.x += gbv.x; v1.y += gbv.y;
            } else if (sel == -1) {
                float2 o0 = *(const float2*)&g_gc[i0];
                float2 o1 = *(const float2*)&g_gc[i1];
                v0.x += o0.x; v0.y += o0.y;
                v1.x += o1.x; v1.y += o1.y;
            }
            *(float2*)&Pout[i0] = v0;
            *(float2*)&Pout[i1] = v1;
        }
    }
}

// ---------------- single-product fp16 GEMM ----------------
// mode: 0 = fp32 C (P slot); 1 = fp16 C + transposed fp16 -> g_YTb; 2 = fp16 -> g_A2f;
//       5 = fp16 C; 6 = fused m1+A2 (y<65 -> mode1 m1; y>=65 -> mode2 A2)
// selB: 0=YTh 1=YTb 9=YTa 2..5=YTq[0..3]
#define KC 32
#define TROW 80
#define TILEB (128*TROW)
#define STAGEB1 (2*TILEB)
#define GEMM1_SMEM (4*STAGEB1)
#define NSTG 64

__global__ void __launch_bounds__(256, 2)
gemm1_kernel(int selA, int selB, int selC, int W, int mode, int batch) {
    extern __shared__ char smem[];
    uint32_t sb = smem_u32(smem);
    int tid = threadIdx.x;
    int wid = tid >> 5;
    int lane = tid & 31;

    int nBlk = blockIdx.y;
    if (batch) {
        int bz = blockIdx.z;
        selA = bz;
        selB = 2 + bz;
        selC = (bz == 0) ? 19 : (bz == 1) ? 20 : (bz == 2) ? 21 : 23;
    }
    if (mode == 6) {
        if (nBlk < 65) { mode = 1; selA = 0; selB = 0; selC = 1; W = XW; }
        else           { mode = 2; selA = 2; selB = 9; W = NN; nBlk -= 65; }
    }
    const __half* Af = selA == 0 ? g_S1f : (selA == 1 ? g_S2f : (selA == 2 ? g_Adf : g_A2f));
    const __half* Bf = selB == 0 ? g_YTh : (selB == 1 ? g_YTb : (selB == 9 ? g_YTa
                        : g_YTq + (size_t)(selB - 2)*QSZ));

    int mBase = blockIdx.x * 128;
    int nBase = nBlk * 128;

    const __half* src[4];
    uint32_t dst[4];
    #pragma unroll
    for (int i = 0; i < 4; i++) {
        int c = tid + i*256;
        int tile = c >> 9;
        int q = c & 511;
        int row = q >> 2, col = q & 3;
        dst[i] = (uint32_t)(tile*TILEB + row*TROW + col*16);
        const __half* base = (tile == 0) ? Af + (size_t)(mBase + row) * NN
                                         : Bf + (size_t)(nBase + row) * NN;
        src[i] = base + col*8;
    }

    #pragma unroll
    for (int s = 0; s < 3; s++) {
        uint32_t so = sb + (uint32_t)(s * STAGEB1);
        #pragma unroll
        for (int i = 0; i < 4; i++) cp16(so + dst[i], src[i] + s*KC);
        cp_commit();
    }

    float acc[4][4][4];
    #pragma unroll
    for (int mf = 0; mf < 4; mf++)
        #pragma unroll
        for (int nf = 0; nf < 4; nf++)
            #pragma unroll
            for (int e = 0; e < 4; e++) acc[mf][nf][e] = 0.f;

    int mw = wid & 1;
    int nw = wid >> 1;
    int a_row = lane & 15;
    int a_colb = (lane >> 4) * 16;
    int b_row = ((lane >> 4) & 1) * 8 + (lane & 7);
    int b_colb = ((lane >> 3) & 1) * 16;

    uint32_t aOff = (uint32_t)((mw*64 + a_row) * TROW) + (uint32_t)a_colb;
    uint32_t bOff = (uint32_t)TILEB + (uint32_t)((nw*32 + b_row) * TROW) + (uint32_t)b_colb;

    for (int s = 0; s < NSTG; s++) {
        cp_wait2();
        __syncthreads();
        int sn = s + 3;
        if (sn < NSTG) {
            uint32_t so2 = sb + (uint32_t)((sn & 3) * STAGEB1);
            #pragma unroll
            for (int i = 0; i < 4; i++) cp16(so2 + dst[i], src[i] + sn*KC);
        }
        cp_commit();

        uint32_t so = sb + (uint32_t)((s & 3) * STAGEB1);
        #pragma unroll
        for (int ks = 0; ks < 2; ks++) {
            uint32_t kb = (uint32_t)(ks*32);
            uint32_t ar[4][4], br[2][4];
            #pragma unroll
            for (int mf = 0; mf < 4; mf++)
                ldm_x4(ar[mf], so + aOff + (uint32_t)(mf*16*TROW) + kb);
            #pragma unroll
            for (int bg = 0; bg < 2; bg++)
                ldm_x4(br[bg], so + bOff + (uint32_t)(bg*16*TROW) + kb);
            #pragma unroll
            for (int mf = 0; mf < 4; mf++) {
                #pragma unroll
                for (int bg = 0; bg < 2; bg++) {
                    mma16816h(acc[mf][bg*2+0], ar[mf], br[bg][0], br[bg][1]);
                    mma16816h(acc[mf][bg*2+1], ar[mf], br[bg][2], br[bg][3]);
                }
            }
        }
    }

    int gid = lane >> 2, tg = lane & 3;

    if (mode == 0) {
        float* C = g_P + (size_t)(selC - 10)*PSZ;
        #pragma unroll
        for (int mf = 0; mf < 4; mf++) {
            int row0 = mBase + mw*64 + mf*16 + gid;
            #pragma unroll
            for (int nf = 0; nf < 4; nf++) {
                int col = nBase + nw*32 + nf*8 + tg*2;
                size_t i0 = (size_t)row0 * W + col;
                size_t i1 = i0 + (size_t)8 * W;
                *(float2*)&C[i0] = make_float2(acc[mf][nf][0], acc[mf][nf][1]);
                *(float2*)&C[i1] = make_float2(acc[mf][nf][2], acc[mf][nf][3]);
            }
        }
    } else if (mode == 2) {
        #pragma unroll
        for (int mf = 0; mf < 4; mf++) {
            int row0 = mBase + mw*64 + mf*16 + gid;
            #pragma unroll
            for (int nf = 0; nf < 4; nf++) {
                int col = nBase + nw*32 + nf*8 + tg*2;
                __half2 v0 = __floats2half2_rn(acc[mf][nf][0], acc[mf][nf][1]);
                __half2 v1 = __floats2half2_rn(acc[mf][nf][2], acc[mf][nf][3]);
                *(__half2*)&g_A2f[(size_t)row0 * NN + col] = v0;
                *(__half2*)&g_A2f[(size_t)(row0 + 8) * NN + col] = v1;
            }
        }
    } else {
        __half* Ch = bufH(selC);
        #pragma unroll
        for (int mf = 0; mf < 4; mf++) {
            int row0 = mBase + mw*64 + mf*16 + gid;
            #pragma unroll
            for (int nf = 0; nf < 4; nf++) {
                int col = nBase + nw*32 + nf*8 + tg*2;
                size_t i0 = (size_t)row0 * W + col;
                size_t i1 = i0 + (size_t)8 * W;
                *(__half2*)&Ch[i0] = __floats2half2_rn(acc[mf][nf][0], acc[mf][nf][1]);
                *(__half2*)&Ch[i1] = __floats2half2_rn(acc[mf][nf][2], acc[mf][nf][3]);
            }
        }
    }

    if (mode == 1) {
        cp_wait0();
        __syncthreads();
        __half* st = (__half*)smem;
        #pragma unroll
        for (int mf = 0; mf < 4; mf++) {
            #pragma unroll
            for (int nf = 0; nf < 4; nf++) {
                int r = mw*64 + mf*16 + gid;
                int c = nw*32 + nf*8 + tg*2;
                st[(c+0)*136 + r]     = __float2half(acc[mf][nf][0]);
                st[(c+1)*136 + r]     = __float2half(acc[mf][nf][1]);
                st[(c+0)*136 + r + 8] = __float2half(acc[mf][nf][2]);
                st[(c+1)*136 + r + 8] = __float2half(acc[mf][nf][3]);
            }
        }
        __syncthreads();
        for (int t = tid; t < 128*16; t += 256) {
            int c = t >> 4, seg = t & 15;
            uint4 v = *(const uint4*)&st[c*136 + seg*8];
            *(uint4*)&g_YTb[(size_t)(nBase + c)*NN + mBase + seg*8] = v;
        }
    }
}

// ---------------- output (fused combine + softmax + hx copy) ----------------
__global__ void __launch_bounds__(256) final_kernel(const float* __restrict__ W,
                                                    const float* __restrict__ bbias,
                                                    const float* __restrict__ hx,
                                                    const float* __restrict__ R,
                                                    float* __restrict__ out, int write_hx) {
    __shared__ float sW[64*64];
    __shared__ float sg[4*64];
    int tid = threadIdx.x;
    int r0 = blockIdx.x * 4;
    int bU = r0 >> 11;
    for (int t = tid; t < 4096; t += 256) sW[t] = W[t];
    {
        int row = r0 + (tid >> 6);
        int d = tid & 63;
        int n = row & 2047;
        int b = row >> 11;
        size_t p = (size_t)n*4096 + (size_t)(b*64 + d);
        float v = g_gc[p]
                + g_P[5*PSZ + p]          // m1 static terms (w1-w4)
                + 2.f*g_P[9*PSZ + p]      // Q2
                + 2.f*g_P[10*PSZ + p]     // Q4
                + g_P[11*PSZ + p]         // Q5
                + g_P[13*PSZ + p];        // Q6
        sg[tid] = v > 0.f ? v : 0.01f * v;
    }
    float l0 = g_logits[bU*4+0], l1 = g_logits[bU*4+1];
    float l2 = g_logits[bU*4+2], l3 = g_logits[bU*4+3];
    float m = fmaxf(fmaxf(l0, l1), fmaxf(l2, l3));
    float e0 = expf(l0 - m), e1 = expf(l1 - m), e2 = expf(l2 - m), e3 = expf(l3 - m);
    float inv = 1.f / (e0 + e1 + e2 + e3);
    float wt[4] = {e0*inv, e1*inv, e2*inv, e3*inv};
    __syncthreads();
    int rl = tid >> 6;
    int d = tid & 63;
    int r = r0 + rl;
    int b = r >> 11;
    int n = r & 2047;
    float acc = 0.f;
    #pragma unroll
    for (int e = 0; e < 64; e++) acc += sg[rl*64 + e] * sW[e*64 + d];
    float att = 0.f;
    #pragma unroll
    for (int k = 0; k < 4; k++) {
        float xv = hx[(size_t)((b << 2) + k)*NDD + (size_t)n*64 + d] + R[(size_t)k*NDD + (size_t)n*64 + d];
        att += xv * wt[k];
    }
    float o = acc + bbias[(size_t)n*64 + d] + att;
    out[(size_t)b*NDD + (size_t)n*64 + d] = o;
    if (write_hx) {
        out[(size_t)OUT1 + (size_t)((b << 2) + 3)*NDD + (size_t)n*64 + d] = o;
        #pragma unroll
        for (int kk = 0; kk < 3; kk++)
            out[(size_t)OUT1 + (size_t)((b << 2) + kk)*NDD + (size_t)n*64 + d] =
                hx[(size_t)((b << 2) + kk + 1)*NDD + (size_t)n*64 + d];
    }
}

// ---------------- launch ----------------
extern "C" void kernel_launch(void* const* d_in, const int* in_sizes, int n_in,
                              void* d_out, int out_size) {
    const float* inputs = (const float*)d_in[0];
    const float* hx     = (const float*)d_in[1];
    const float* graph  = (const float*)d_in[2];
    const float* nv1    = (const float*)d_in[3];
    const float* nv2    = (const float*)d_in[4];
    const float* W      = (const float*)d_in[5];
    const float* bbias  = (const float*)d_in[6];
    const float* R      = (const float*)d_in[7];
    const float* gw     = (const float*)d_in[8];
    const float* gb     = (const float*)d_in[9];
    const float* aw     = (const float*)d_in[10];
    const float* ab     = (const float*)d_in[11];
    float* out = (float*)d_out;

    int write_hx = ((size_t)out_size >= FULL_OUT) ? 1 : 0;

    cudaFuncSetAttribute(gemm1_kernel, cudaFuncAttributeMaxDynamicSharedMemorySize, GEMM1_SMEM);
    cudaFuncSetAttribute(tcproj_kernel, cudaFuncAttributeMaxDynamicSharedMemorySize, TPROJ_SMEM);

    dim3 gm1a2(NN/128, 65 + 16);
    dim3 gfull(NN/128, XW/128);
    dim3 gleaf(NN/128, 4096/128, 4);
    dim3 xcomb((XW + NN)/32, NN/32);
    dim3 xqb(4096/32, NN/32, 4);
    dim3 xblk(32, 8);

    rowsum_dinv_kernel<<<NN, 256>>>(graph);
    colsum_part_kernel<<<dim3(NN/256, 8), 256>>>(graph);
    colsum_fin_kernel<<<NN/256, 256>>>();
    build_S1_kernel<<<dim3(64, 64), dim3(32, 8)>>>(graph);
    build_S2_kernel<<<(NN*NN)/256, 256>>>(graph);
    adp_kernel<<<NN, 256>>>(nv1, nv2);
    gw_prep_kernel<<<(7*64*KP + 255)/256, 256>>>(gw);

    build_x0_logits_kernel<<<X0BLKS + BB*4, 256>>>(inputs, hx, R, aw, ab);

    xp_kernel<<<NN, 256>>>(0, 0);
    tcproj_kernel<<<dim3(1024, 1), 256, TPROJ_SMEM>>>(0, 0, make_int4(-2, 0, 0, 0), gb);

    xt_comb_kernel<<<xcomb, xblk>>>();

    gemm1_kernel<<<gm1a2, 256, GEMM1_SMEM>>>(0, 0, 0, 0, 6, 0);

    gemm1_kernel<<<gfull, 256, GEMM1_SMEM>>>(1, 1, 2, XW, 5, 0);

    xp_kernel<<<dim3(NN, 2), 256>>>(0, 1);
    tcproj_kernel<<<dim3(1024, 6), 256, TPROJ_SMEM>>>(1, 0, make_int4(0, 0, 0, 0), gb);

    xt_f16_batch_kernel<<<xqb, xblk>>>();
    gemm1_kernel<<<gleaf, 256, GEMM1_SMEM>>>(0, 0, 0, 4096, 0, 1);

    final_kernel<<<(BB*NN)/4, 256>>>(W, bbias, hx, R, out, write_hx);
}